// round 7
// baseline (speedup 1.0000x reference)
#include <cuda_runtime.h>
#include <cuda_bf16.h>
#include <math.h>
#include <stdint.h>

#define NN 262144
#define DD 256
#define DOUT 128
#define SEGS 4096

// ---------------- device scratch (no allocations allowed) -------------------
__device__ __nv_bfloat16 g_h_hi[(size_t)NN * DD];  // split-bf16 h
__device__ __nv_bfloat16 g_h_lo[(size_t)NN * DD];
__device__ float g_s[(size_t)NN * DD];   // scores s
__device__ float g_sx[SEGS * DD];        // segment-weighted sums
__device__ float g_h2[SEGS * DD];        // readout hidden
__device__ int   g_offs[SEGS + 1];       // segment start offsets
// pre-transposed split-bf16 weights, layout [n][k] (K contiguous)
__device__ __nv_bfloat16 g_w1t_hi[DD * DD], g_w1t_lo[DD * DD];
__device__ __nv_bfloat16 g_w2t_hi[DD * DD], g_w2t_lo[DD * DD];

// ---------------- helpers ---------------------------------------------------
__device__ __forceinline__ uint32_t smem_u32(const void* p) {
    uint32_t a;
    asm("{ .reg .u64 t; cvta.to.shared.u64 t, %1; cvt.u32.u64 %0, t; }"
        : "=r"(a) : "l"(p));
    return a;
}

__device__ __forceinline__ void ldm_x4(uint32_t* r, uint32_t addr) {
    asm volatile("ldmatrix.sync.aligned.m8n8.x4.shared.b16 {%0,%1,%2,%3}, [%4];"
                 : "=r"(r[0]), "=r"(r[1]), "=r"(r[2]), "=r"(r[3]) : "r"(addr));
}

__device__ __forceinline__ void mma16816(float* c, const uint32_t* a,
                                         uint32_t b0, uint32_t b1) {
    asm volatile(
        "mma.sync.aligned.m16n8k16.row.col.f32.bf16.bf16.f32 "
        "{%0,%1,%2,%3}, {%4,%5,%6,%7}, {%8,%9}, {%0,%1,%2,%3};"
        : "+f"(c[0]), "+f"(c[1]), "+f"(c[2]), "+f"(c[3])
        : "r"(a[0]), "r"(a[1]), "r"(a[2]), "r"(a[3]), "r"(b0), "r"(b1));
}

__device__ __forceinline__ uint32_t pack_bf16x2(float x, float y) {
    __nv_bfloat16 hx = __float2bfloat16(x);
    __nv_bfloat16 hy = __float2bfloat16(y);
    return (uint32_t)__bfloat16_as_ushort(hx) |
           ((uint32_t)__bfloat16_as_ushort(hy) << 16);
}

#define CP_ASYNC16(dst, src) \
    asm volatile("cp.async.cg.shared.global [%0], [%1], 16;" \
                 :: "r"(dst), "l"(src) : "memory")
#define CP_COMMIT() asm volatile("cp.async.commit_group;" ::: "memory")
#define CP_WAIT(n)  asm volatile("cp.async.wait_group %0;" :: "n"(n) : "memory")

// ---------------------------------------------------------------------------
__global__ void prep_weights_kernel(const float* __restrict__ W1,
                                    const float* __restrict__ W2)
{
    int n = blockIdx.x;
    int k = threadIdx.x;
    const float* W = (blockIdx.y == 0) ? W1 : W2;
    __nv_bfloat16* Whi = (blockIdx.y == 0) ? g_w1t_hi : g_w2t_hi;
    __nv_bfloat16* Wlo = (blockIdx.y == 0) ? g_w1t_lo : g_w2t_lo;
    float v = W[k * DD + n];
    __nv_bfloat16 hi = __float2bfloat16(v);
    float lo = v - __bfloat162float(hi);
    Whi[n * DD + k] = hi;
    Wlo[n * DD + k] = __float2bfloat16(lo);
}

__global__ void seg_offsets_kernel(const int* __restrict__ index, int* __restrict__ offs)
{
    int b = blockIdx.x * blockDim.x + threadIdx.x;
    if (b > SEGS) return;
    int lo = 0, hi = NN;
    while (lo < hi) {
        int mid = (lo + hi) >> 1;
        if (index[mid] < b) lo = mid + 1;
        else hi = mid;
    }
    offs[b] = lo;
}

// ---------------------------------------------------------------------------
// 3-stage pipelined mma.sync split-bf16 GEMM.
//  Stage row layout: [32 hi b16 (64B) | 32 lo b16 (64B) | 16B pad] = 144 B.
//  Stage = A(128 rows) + B(128 rows) = 36864 B; 3 stages = 108 KB.
// ---------------------------------------------------------------------------
#define RS    144               // bytes per row
#define LOFF  64                // lo-half byte offset within row
#define OB    (128 * RS)        // B offset within stage
#define STG   (256 * RS)        // stage size = 36864
#define NSTG  3
#define NC    8                 // K chunks of 32

template <int EPI, bool ASPLIT, bool WSPLIT>
__global__ __launch_bounds__(256, 2)
void mma_gemm_pipe(const float* __restrict__ A32,
                   const __nv_bfloat16* __restrict__ Ahi,
                   const __nv_bfloat16* __restrict__ Alo,
                   const __nv_bfloat16* __restrict__ Whi,
                   const __nv_bfloat16* __restrict__ Wlo,
                   const float* __restrict__ bias,
                   float* __restrict__ C,
                   __nv_bfloat16* __restrict__ Chi,
                   __nv_bfloat16* __restrict__ Clo)
{
    extern __shared__ char dsm[];
    const uint32_t sb = smem_u32(dsm);

    const int tid  = threadIdx.x;
    const int lane = tid & 31;
    const int wid  = tid >> 5;
    const int wm   = wid & 3;
    const int wn   = wid >> 2;
    const int mtile = blockIdx.x * 128;
    const int ntile = blockIdx.y * 128;

    float acc[2][8][4];
#pragma unroll
    for (int i = 0; i < 2; i++)
#pragma unroll
        for (int j = 0; j < 8; j++)
#pragma unroll
            for (int q = 0; q < 4; q++) acc[i][j][q] = 0.0f;

    const int a_row = (lane & 15);
    const int a_ko  = (lane & 16) ? 8 : 0;
    const int b_row = (lane & 7) + ((lane & 16) ? 8 : 0);
    const int b_ko  = (lane & 8) ? 8 : 0;

    // ---- load helpers -------------------------------------------------------
    auto cpB = [&](int kc, uint32_t stg) {
        const int k0 = kc * 32;
#pragma unroll
        for (int t = 0; t < 2; t++) {
            int idx = tid + t * 256;          // 512 uint4 = 128 rows x 4
            int r = idx >> 2, c = idx & 3;
            size_t g = (size_t)(ntile + r) * DD + k0 + c * 8;
            uint32_t so = stg + OB + (uint32_t)r * RS + c * 16;
            CP_ASYNC16(so,        Whi + g);
            CP_ASYNC16(so + LOFF, Wlo + g);
        }
    };
    auto cpA = [&](int kc, uint32_t stg) {   // ASPLIT path
        const int k0 = kc * 32;
#pragma unroll
        for (int t = 0; t < 2; t++) {
            int idx = tid + t * 256;
            int r = idx >> 2, c = idx & 3;
            size_t g = (size_t)(mtile + r) * DD + k0 + c * 8;
            uint32_t so = stg + (uint32_t)r * RS + c * 16;
            CP_ASYNC16(so,        Ahi + g);
            CP_ASYNC16(so + LOFF, Alo + g);
        }
    };
    float4 ra[4];
    auto ldgA = [&](int kc) {                // !ASPLIT: fp32 A into regs
        const int k0 = kc * 32;
#pragma unroll
        for (int t = 0; t < 4; t++) {
            int idx = tid + t * 256;
            int r = idx >> 3, c = idx & 7;
            ra[t] = *reinterpret_cast<const float4*>(
                &A32[(size_t)(mtile + r) * DD + k0 + c * 4]);
        }
    };
    auto stcvA = [&](uint32_t stgoff) {      // convert regs -> split bf16 smem
#pragma unroll
        for (int t = 0; t < 4; t++) {
            int idx = tid + t * 256;
            int r = idx >> 3, c = idx & 7;   // c: float4 within row -> 8B
            float4 v = ra[t];
            float hx = __bfloat162float(__float2bfloat16(v.x));
            float hy = __bfloat162float(__float2bfloat16(v.y));
            float hz = __bfloat162float(__float2bfloat16(v.z));
            float hw = __bfloat162float(__float2bfloat16(v.w));
            uint2 ph, pl;
            ph.x = pack_bf16x2(v.x, v.y);
            ph.y = pack_bf16x2(v.z, v.w);
            pl.x = pack_bf16x2(v.x - hx, v.y - hy);
            pl.y = pack_bf16x2(v.z - hz, v.w - hw);
            uint32_t so = stgoff + (uint32_t)r * RS + c * 8;
            *reinterpret_cast<uint2*>(dsm + so)        = ph;
            *reinterpret_cast<uint2*>(dsm + so + LOFF) = pl;
        }
    };
    auto compute = [&](uint32_t stg) {
        const uint32_t bA = stg;
        const uint32_t bB = stg + OB;
#pragma unroll
        for (int ks = 0; ks < 2; ks++) {
            const int kb = ks * 16;
            uint32_t a_hi[2][4], a_lo[2][4];
#pragma unroll
            for (int mb = 0; mb < 2; mb++) {
                int row = wm * 32 + mb * 16 + a_row;
                uint32_t off = bA + (uint32_t)row * RS + (kb + a_ko) * 2;
                ldm_x4(a_hi[mb], off);
                ldm_x4(a_lo[mb], off + LOFF);
            }
#pragma unroll
            for (int g = 0; g < 4; g++) {
                int n = wn * 64 + g * 16 + b_row;
                uint32_t off = bB + (uint32_t)n * RS + (kb + b_ko) * 2;
                uint32_t bh[4], bl[4];
                ldm_x4(bh, off);
                ldm_x4(bl, off + LOFF);
#pragma unroll
                for (int mb = 0; mb < 2; mb++) {
#pragma unroll
                    for (int nb = 0; nb < 2; nb++) {
                        float* c = acc[mb][g * 2 + nb];
                        mma16816(c, a_hi[mb], bh[nb * 2], bh[nb * 2 + 1]);
                        mma16816(c, a_hi[mb], bl[nb * 2], bl[nb * 2 + 1]);
                        mma16816(c, a_lo[mb], bh[nb * 2], bh[nb * 2 + 1]);
                    }
                }
            }
        }
    };

    // ---- prologue: stages 0 and 1 ------------------------------------------
    const uint32_t stg0 = sb, stg1 = sb + STG, stg2 = sb + 2 * STG;
    const uint32_t stgs[NSTG] = {stg0, stg1, stg2};
    if (!ASPLIT) {
        ldgA(0); stcvA(0);
        ldgA(1); stcvA(STG);
        cpB(0, stg0); CP_COMMIT();           // group: chunk 0
        cpB(1, stg1); CP_COMMIT();           // group: chunk 1
        ldgA(2);                             // ra holds chunk 2
    } else {
        cpA(0, stg0); cpB(0, stg0); CP_COMMIT();
        cpA(1, stg1); cpB(1, stg1); CP_COMMIT();
    }

    // ---- mainloop: wait only for chunk kc; kc+1 stays in flight -------------
#pragma unroll
    for (int kc = 0; kc < NC; kc++) {
        if (kc + 1 < NC) { CP_WAIT(1); } else { CP_WAIT(0); }
        __syncthreads();

        if (kc + 2 < NC) {
            const uint32_t nstg = stgs[(kc + 2) % NSTG];
            if (!ASPLIT) {
                stcvA(nstg - sb);                 // chunk kc+2 from ra
                cpB(kc + 2, nstg); CP_COMMIT();
                if (kc + 3 < NC) ldgA(kc + 3);    // refill ra
            } else {
                cpA(kc + 2, nstg); cpB(kc + 2, nstg); CP_COMMIT();
            }
        } else {
            CP_COMMIT();                          // keep group numbering aligned
        }

        compute(stgs[kc % NSTG]);
    }

    // ---- epilogue -----------------------------------------------------------
    const int gq  = lane >> 2;
    const int tc2 = (lane & 3) * 2;
#pragma unroll
    for (int mb = 0; mb < 2; mb++) {
        int r0 = mtile + wm * 32 + mb * 16 + gq;
#pragma unroll
        for (int nb = 0; nb < 8; nb++) {
            int col = ntile + wn * 64 + nb * 8 + tc2;
            float bv0 = bias[col], bv1 = bias[col + 1];
            float z0 = acc[mb][nb][0] + bv0;
            float z1 = acc[mb][nb][1] + bv1;
            float z2 = acc[mb][nb][2] + bv0;
            float z3 = acc[mb][nb][3] + bv1;
            if (EPI == 1) {
                z0 = z0 * (1.0f / (1.0f + __expf(-z0)));
                z1 = z1 * (1.0f / (1.0f + __expf(-z1)));
                z2 = z2 * (1.0f / (1.0f + __expf(-z2)));
                z3 = z3 * (1.0f / (1.0f + __expf(-z3)));
            }
            if (WSPLIT) {
                float h0 = __bfloat162float(__float2bfloat16(z0));
                float h1 = __bfloat162float(__float2bfloat16(z1));
                float h2v = __bfloat162float(__float2bfloat16(z2));
                float h3 = __bfloat162float(__float2bfloat16(z3));
                *reinterpret_cast<uint32_t*>(&Chi[(size_t)r0 * DD + col]) =
                    pack_bf16x2(z0, z1);
                *reinterpret_cast<uint32_t*>(&Clo[(size_t)r0 * DD + col]) =
                    pack_bf16x2(z0 - h0, z1 - h1);
                *reinterpret_cast<uint32_t*>(&Chi[(size_t)(r0 + 8) * DD + col]) =
                    pack_bf16x2(z2, z3);
                *reinterpret_cast<uint32_t*>(&Clo[(size_t)(r0 + 8) * DD + col]) =
                    pack_bf16x2(z2 - h2v, z3 - h3);
            } else {
                *reinterpret_cast<float2*>(&C[(size_t)r0 * DD + col]) =
                    make_float2(z0, z1);
                *reinterpret_cast<float2*>(&C[(size_t)(r0 + 8) * DD + col]) =
                    make_float2(z2, z3);
            }
        }
    }
}

// ---------------------------------------------------------------------------
// fp32 SIMT GEMM for the small readout MLP
// ---------------------------------------------------------------------------
template <int EPI>
__global__ __launch_bounds__(256, 2)
void gemm128(const float* __restrict__ A, const float* __restrict__ B,
             const float* __restrict__ bias, float* __restrict__ C,
             int M, int Ncols, int K)
{
    constexpr int BM = 128, BN = 128, BK = 16;
    __shared__ float As[BK][BM + 4];
    __shared__ float Bs[BK][BN + 4];

    const int mtile = blockIdx.x * BM;
    const int ntile = blockIdx.y * BN;
    const int tid = threadIdx.x;
    const int trow = tid >> 4;
    const int tcol = tid & 15;

    float acc[8][8];
#pragma unroll
    for (int i = 0; i < 8; i++)
#pragma unroll
        for (int j = 0; j < 8; j++) acc[i][j] = 0.0f;

    for (int k0 = 0; k0 < K; k0 += BK) {
#pragma unroll
        for (int t = 0; t < 2; t++) {
            int f4 = tid + t * 256;
            int r = f4 >> 2;
            int c = (f4 & 3) * 4;
            float4 v = *reinterpret_cast<const float4*>(
                &A[(size_t)(mtile + r) * K + k0 + c]);
            As[c + 0][r] = v.x;
            As[c + 1][r] = v.y;
            As[c + 2][r] = v.z;
            As[c + 3][r] = v.w;
        }
#pragma unroll
        for (int t = 0; t < 2; t++) {
            int f4 = tid + t * 256;
            int r = f4 >> 5;
            int c = (f4 & 31) * 4;
            float4 v = *reinterpret_cast<const float4*>(
                &B[(size_t)(k0 + r) * Ncols + ntile + c]);
            *reinterpret_cast<float4*>(&Bs[r][c]) = v;
        }
        __syncthreads();

#pragma unroll
        for (int kk = 0; kk < BK; kk++) {
            float a[8], b[8];
            float4 a0 = *reinterpret_cast<const float4*>(&As[kk][trow * 8]);
            float4 a1 = *reinterpret_cast<const float4*>(&As[kk][trow * 8 + 4]);
            float4 b0 = *reinterpret_cast<const float4*>(&Bs[kk][tcol * 8]);
            float4 b1 = *reinterpret_cast<const float4*>(&Bs[kk][tcol * 8 + 4]);
            a[0]=a0.x; a[1]=a0.y; a[2]=a0.z; a[3]=a0.w;
            a[4]=a1.x; a[5]=a1.y; a[6]=a1.z; a[7]=a1.w;
            b[0]=b0.x; b[1]=b0.y; b[2]=b0.z; b[3]=b0.w;
            b[4]=b1.x; b[5]=b1.y; b[6]=b1.z; b[7]=b1.w;
#pragma unroll
            for (int i = 0; i < 8; i++)
#pragma unroll
                for (int j = 0; j < 8; j++)
                    acc[i][j] = fmaf(a[i], b[j], acc[i][j]);
        }
        __syncthreads();
    }

    float bv[8];
#pragma unroll
    for (int j = 0; j < 8; j++) bv[j] = bias[ntile + tcol * 8 + j];

#pragma unroll
    for (int i = 0; i < 8; i++) {
        int row = mtile + trow * 8 + i;
        float v[8];
#pragma unroll
        for (int j = 0; j < 8; j++) {
            float z = acc[i][j] + bv[j];
            if (EPI == 1) z = z * (1.0f / (1.0f + __expf(-z)));
            v[j] = z;
        }
        float* cp = &C[(size_t)row * Ncols + ntile + tcol * 8];
        *reinterpret_cast<float4*>(cp)     = make_float4(v[0], v[1], v[2], v[3]);
        *reinterpret_cast<float4*>(cp + 4) = make_float4(v[4], v[5], v[6], v[7]);
    }
}

// ---------------------------------------------------------------------------
// Fused segment softmax-weighted sum, dual independent online-softmax chains
// ---------------------------------------------------------------------------
__global__ __launch_bounds__(256)
void segment_softmax_kernel(const float* __restrict__ s, const float* __restrict__ x,
                            const int* __restrict__ offs, float* __restrict__ sx)
{
    int b = blockIdx.x;
    int d = threadIdx.x;
    int start = offs[b], end = offs[b + 1];

    const float* sp = s + (size_t)start * DD + d;
    const float* xp = x + (size_t)start * DD + d;

    float m0 = -INFINITY, se0 = 0.0f, sex0 = 0.0f;
    float m1 = -INFINITY, se1 = 0.0f, sex1 = 0.0f;

    int i = start;
    for (; i + 1 < end; i += 2) {
        float sv0 = sp[0],  xv0 = xp[0];
        float sv1 = sp[DD], xv1 = xp[DD];
        sp += 2 * DD; xp += 2 * DD;
        if (sv0 > m0) {
            float c = __expf(m0 - sv0);
            se0 = se0 * c + 1.0f; sex0 = sex0 * c + xv0; m0 = sv0;
        } else {
            float e = __expf(sv0 - m0);
            se0 += e; sex0 += e * xv0;
        }
        if (sv1 > m1) {
            float c = __expf(m1 - sv1);
            se1 = se1 * c + 1.0f; sex1 = sex1 * c + xv1; m1 = sv1;
        } else {
            float e = __expf(sv1 - m1);
            se1 += e; sex1 += e * xv1;
        }
    }
    if (i < end) {
        float sv0 = sp[0], xv0 = xp[0];
        if (sv0 > m0) {
            float c = __expf(m0 - sv0);
            se0 = se0 * c + 1.0f; sex0 = sex0 * c + xv0; m0 = sv0;
        } else {
            float e = __expf(sv0 - m0);
            se0 += e; sex0 += e * xv0;
        }
    }

    float r = 0.0f;
    if (end > start) {
        float m = fmaxf(m0, m1);
        float c0 = __expf(m0 - m);                 // chain0 nonempty
        float c1 = (m1 == -INFINITY) ? 0.0f : __expf(m1 - m);
        float se  = se0 * c0 + se1 * c1;
        float sex = sex0 * c0 + sex1 * c1;
        r = sex / se;
    }
    sx[b * DD + d] = r;
}

// ---------------------------------------------------------------------------
extern "C" void kernel_launch(void* const* d_in, const int* in_sizes, int n_in,
                              void* d_out, int out_size)
{
    const float* x     = (const float*)d_in[0];
    const int*   index = (const int*)  d_in[1];
    const float* W1    = (const float*)d_in[2];
    const float* b1    = (const float*)d_in[3];
    const float* W2    = (const float*)d_in[4];
    const float* b2    = (const float*)d_in[5];
    const float* W3    = (const float*)d_in[6];
    const float* b3    = (const float*)d_in[7];
    const float* W4    = (const float*)d_in[8];
    const float* b4    = (const float*)d_in[9];
    float* out = (float*)d_out;

    float *s, *sx, *h2;
    int* offs;
    __nv_bfloat16 *hh, *hl, *w1h, *w1l, *w2h, *w2l;
    cudaGetSymbolAddress((void**)&hh,   g_h_hi);
    cudaGetSymbolAddress((void**)&hl,   g_h_lo);
    cudaGetSymbolAddress((void**)&s,    g_s);
    cudaGetSymbolAddress((void**)&sx,   g_sx);
    cudaGetSymbolAddress((void**)&h2,   g_h2);
    cudaGetSymbolAddress((void**)&offs, g_offs);
    cudaGetSymbolAddress((void**)&w1h,  g_w1t_hi);
    cudaGetSymbolAddress((void**)&w1l,  g_w1t_lo);
    cudaGetSymbolAddress((void**)&w2h,  g_w2t_hi);
    cudaGetSymbolAddress((void**)&w2l,  g_w2t_lo);

    cudaFuncSetAttribute((const void*)mma_gemm_pipe<1, false, true>,
                         cudaFuncAttributeMaxDynamicSharedMemorySize, NSTG * STG);
    cudaFuncSetAttribute((const void*)mma_gemm_pipe<0, true, false>,
                         cudaFuncAttributeMaxDynamicSharedMemorySize, NSTG * STG);

    // 0. split/transpose weights
    prep_weights_kernel<<<dim3(DD, 2), DD>>>(W1, W2);

    // 1. segment boundaries
    seg_offsets_kernel<<<(SEGS + 1 + 255) / 256, 256>>>(index, offs);

    // 2. h = silu(x @ W1 + b1) -> split bf16 (3-stage pipelined mma.sync)
    mma_gemm_pipe<1, false, true><<<dim3(NN / 128, 2), 256, NSTG * STG>>>(
        x, nullptr, nullptr, w1h, w1l, b1, nullptr, hh, hl);

    // 3. s = h @ W2 + b2  (A pre-split, cp.async everywhere)
    mma_gemm_pipe<0, true, false><<<dim3(NN / 128, 2), 256, NSTG * STG>>>(
        nullptr, hh, hl, w2h, w2l, b2, s, nullptr, nullptr);

    // 4. fused scatter-softmax + weighted segment sum
    segment_softmax_kernel<<<SEGS, 256>>>(s, x, offs, sx);

    // 5. h2 = silu(sx @ W3 + b3)
    gemm128<1><<<dim3(SEGS / 128, DD / 128), 256>>>(sx, W3, b3, h2, SEGS, DD, DD);

    // 6. out = h2 @ W4 + b4
    gemm128<0><<<dim3(SEGS / 128, DOUT / 128), 256>>>(h2, W4, b4, out, SEGS, DOUT, DD);
}

// round 8
// speedup vs baseline: 1.0360x; 1.0360x over previous
#include <cuda_runtime.h>
#include <cuda_bf16.h>
#include <math.h>
#include <stdint.h>

#define NN 262144
#define DD 256
#define DOUT 128
#define SEGS 4096

// ---------------- device scratch (no allocations allowed) -------------------
__device__ __nv_bfloat16 g_h_hi[(size_t)NN * DD];  // split-bf16 h
__device__ __nv_bfloat16 g_h_lo[(size_t)NN * DD];
__device__ float g_s[(size_t)NN * DD];   // scores s
__device__ float g_sx[SEGS * DD];        // segment-weighted sums
__device__ float g_h2[SEGS * DD];        // readout hidden
__device__ int   g_offs[SEGS + 1];       // segment start offsets
// pre-transposed split-bf16 weights, layout [n][k] (K contiguous)
__device__ __nv_bfloat16 g_w1t_hi[DD * DD], g_w1t_lo[DD * DD];
__device__ __nv_bfloat16 g_w2t_hi[DD * DD], g_w2t_lo[DD * DD];

// ---------------- helpers ---------------------------------------------------
__device__ __forceinline__ uint32_t smem_u32(const void* p) {
    uint32_t a;
    asm("{ .reg .u64 t; cvta.to.shared.u64 t, %1; cvt.u32.u64 %0, t; }"
        : "=r"(a) : "l"(p));
    return a;
}

__device__ __forceinline__ void ldm_x4(uint32_t* r, uint32_t addr) {
    asm volatile("ldmatrix.sync.aligned.m8n8.x4.shared.b16 {%0,%1,%2,%3}, [%4];"
                 : "=r"(r[0]), "=r"(r[1]), "=r"(r[2]), "=r"(r[3]) : "r"(addr));
}

__device__ __forceinline__ void mma16816(float* c, const uint32_t* a,
                                         uint32_t b0, uint32_t b1) {
    asm volatile(
        "mma.sync.aligned.m16n8k16.row.col.f32.bf16.bf16.f32 "
        "{%0,%1,%2,%3}, {%4,%5,%6,%7}, {%8,%9}, {%0,%1,%2,%3};"
        : "+f"(c[0]), "+f"(c[1]), "+f"(c[2]), "+f"(c[3])
        : "r"(a[0]), "r"(a[1]), "r"(a[2]), "r"(a[3]), "r"(b0), "r"(b1));
}

__device__ __forceinline__ uint32_t pack_bf16x2(float x, float y) {
    __nv_bfloat16 hx = __float2bfloat16(x);
    __nv_bfloat16 hy = __float2bfloat16(y);
    return (uint32_t)__bfloat16_as_ushort(hx) |
           ((uint32_t)__bfloat16_as_ushort(hy) << 16);
}

#define CP_ASYNC16(dst, src) \
    asm volatile("cp.async.cg.shared.global [%0], [%1], 16;" \
                 :: "r"(dst), "l"(src) : "memory")
#define CP_COMMIT() asm volatile("cp.async.commit_group;" ::: "memory")
#define CP_WAIT(n)  asm volatile("cp.async.wait_group %0;" :: "n"(n) : "memory")

// ---------------------------------------------------------------------------
__global__ void prep_weights_kernel(const float* __restrict__ W1,
                                    const float* __restrict__ W2)
{
    int n = blockIdx.x;
    int k = threadIdx.x;
    const float* W = (blockIdx.y == 0) ? W1 : W2;
    __nv_bfloat16* Whi = (blockIdx.y == 0) ? g_w1t_hi : g_w2t_hi;
    __nv_bfloat16* Wlo = (blockIdx.y == 0) ? g_w1t_lo : g_w2t_lo;
    float v = W[k * DD + n];
    __nv_bfloat16 hi = __float2bfloat16(v);
    float lo = v - __bfloat162float(hi);
    Whi[n * DD + k] = hi;
    Wlo[n * DD + k] = __float2bfloat16(lo);
}

__global__ void seg_offsets_kernel(const int* __restrict__ index, int* __restrict__ offs)
{
    int b = blockIdx.x * blockDim.x + threadIdx.x;
    if (b > SEGS) return;
    int lo = 0, hi = NN;
    while (lo < hi) {
        int mid = (lo + hi) >> 1;
        if (index[mid] < b) lo = mid + 1;
        else hi = mid;
    }
    offs[b] = lo;
}

// ---------------------------------------------------------------------------
// Pipelined mma.sync split-bf16 GEMM, single-sync mainloop (round-5 layout),
// with pass-major MMA ordering for accumulator ILP.
// ---------------------------------------------------------------------------
#define PADK 40
#define STG   40960              // bytes per stage (4 arrays * 128*PADK*2)
#define OAHI  0
#define OALO  10240
#define OBHI  20480
#define OBLO  30720
#define NC    8                  // K chunks of 32

template <int EPI, bool ASPLIT, bool WSPLIT>
__global__ __launch_bounds__(256, 2)
void mma_gemm_pipe(const float* __restrict__ A32,
                   const __nv_bfloat16* __restrict__ Ahi,
                   const __nv_bfloat16* __restrict__ Alo,
                   const __nv_bfloat16* __restrict__ Whi,
                   const __nv_bfloat16* __restrict__ Wlo,
                   const float* __restrict__ bias,
                   float* __restrict__ C,
                   __nv_bfloat16* __restrict__ Chi,
                   __nv_bfloat16* __restrict__ Clo)
{
    extern __shared__ char dsm[];
    const uint32_t sb = smem_u32(dsm);

    const int tid  = threadIdx.x;
    const int lane = tid & 31;
    const int wid  = tid >> 5;
    const int wm   = wid & 3;
    const int wn   = wid >> 2;
    const int mtile = blockIdx.x * 128;
    const int ntile = blockIdx.y * 128;

    float acc[2][8][4];
#pragma unroll
    for (int i = 0; i < 2; i++)
#pragma unroll
        for (int j = 0; j < 8; j++)
#pragma unroll
            for (int q = 0; q < 4; q++) acc[i][j][q] = 0.0f;

    const int a_row = (lane & 15);
    const int a_ko  = (lane & 16) ? 8 : 0;
    const int b_row = (lane & 7) + ((lane & 16) ? 8 : 0);
    const int b_ko  = (lane & 8) ? 8 : 0;

    // ---- load helpers -------------------------------------------------------
    auto cpB = [&](int kc, uint32_t stg) {
        const int k0 = kc * 32;
#pragma unroll
        for (int t = 0; t < 2; t++) {
            int idx = tid + t * 256;
            int r = idx >> 2, c = idx & 3;
            size_t g = (size_t)(ntile + r) * DD + k0 + c * 8;
            uint32_t so = (uint32_t)(r * PADK + c * 8) * 2;
            CP_ASYNC16(stg + OBHI + so, Whi + g);
            CP_ASYNC16(stg + OBLO + so, Wlo + g);
        }
    };
    auto cpA = [&](int kc, uint32_t stg) {   // ASPLIT path
        const int k0 = kc * 32;
#pragma unroll
        for (int t = 0; t < 2; t++) {
            int idx = tid + t * 256;
            int r = idx >> 2, c = idx & 3;
            size_t g = (size_t)(mtile + r) * DD + k0 + c * 8;
            uint32_t so = (uint32_t)(r * PADK + c * 8) * 2;
            CP_ASYNC16(stg + OAHI + so, Ahi + g);
            CP_ASYNC16(stg + OALO + so, Alo + g);
        }
    };
    float4 ra[4];
    auto ldgA = [&](int kc) {                // !ASPLIT: fp32 A into regs
        const int k0 = kc * 32;
#pragma unroll
        for (int t = 0; t < 4; t++) {
            int idx = tid + t * 256;
            int r = idx >> 3, c = idx & 7;
            ra[t] = *reinterpret_cast<const float4*>(
                &A32[(size_t)(mtile + r) * DD + k0 + c * 4]);
        }
    };
    auto stcvA = [&](uint32_t stg) {         // convert regs -> split bf16 smem
#pragma unroll
        for (int t = 0; t < 4; t++) {
            int idx = tid + t * 256;
            int r = idx >> 3, c = idx & 7;
            float4 v = ra[t];
            float hx = __bfloat162float(__float2bfloat16(v.x));
            float hy = __bfloat162float(__float2bfloat16(v.y));
            float hz = __bfloat162float(__float2bfloat16(v.z));
            float hw = __bfloat162float(__float2bfloat16(v.w));
            uint2 ph, pl;
            ph.x = pack_bf16x2(v.x, v.y);
            ph.y = pack_bf16x2(v.z, v.w);
            pl.x = pack_bf16x2(v.x - hx, v.y - hy);
            pl.y = pack_bf16x2(v.z - hz, v.w - hw);
            uint32_t so = (uint32_t)(r * PADK + c * 4) * 2;
            *reinterpret_cast<uint2*>(dsm + (stg - sb) + OAHI + so) = ph;
            *reinterpret_cast<uint2*>(dsm + (stg - sb) + OALO + so) = pl;
        }
    };
    auto compute = [&](uint32_t stg) {
        const uint32_t bAhi = stg + OAHI, bAlo = stg + OALO;
        const uint32_t bBhi = stg + OBHI, bBlo = stg + OBLO;
#pragma unroll
        for (int ks = 0; ks < 2; ks++) {
            const int kb = ks * 16;
            uint32_t a_hi[2][4], a_lo[2][4];
#pragma unroll
            for (int mb = 0; mb < 2; mb++) {
                int row = wm * 32 + mb * 16 + a_row;
                uint32_t off = (uint32_t)(row * PADK + kb + a_ko) * 2;
                ldm_x4(a_hi[mb], bAhi + off);
                ldm_x4(a_lo[mb], bAlo + off);
            }
#pragma unroll
            for (int g = 0; g < 4; g++) {
                int n = wn * 64 + g * 16 + b_row;
                uint32_t off = (uint32_t)(n * PADK + kb + b_ko) * 2;
                uint32_t bh[4], bl[4];
                ldm_x4(bh, bBhi + off);
                ldm_x4(bl, bBlo + off);
                // pass-major: same-acc MMAs are 4 apart -> acc ILP
#pragma unroll
                for (int mb = 0; mb < 2; mb++)
#pragma unroll
                    for (int nb = 0; nb < 2; nb++)
                        mma16816(acc[mb][g * 2 + nb], a_hi[mb],
                                 bh[nb * 2], bh[nb * 2 + 1]);
#pragma unroll
                for (int mb = 0; mb < 2; mb++)
#pragma unroll
                    for (int nb = 0; nb < 2; nb++)
                        mma16816(acc[mb][g * 2 + nb], a_hi[mb],
                                 bl[nb * 2], bl[nb * 2 + 1]);
#pragma unroll
                for (int mb = 0; mb < 2; mb++)
#pragma unroll
                    for (int nb = 0; nb < 2; nb++)
                        mma16816(acc[mb][g * 2 + nb], a_lo[mb],
                                 bh[nb * 2], bh[nb * 2 + 1]);
            }
        }
    };

    // ---- prologue: stage 0 resident, (GEMM1) chunk 1 in regs ---------------
    const uint32_t st0 = sb, st1 = sb + STG;
    if (!ASPLIT) {
        ldgA(0); stcvA(st0);
        cpB(0, st0); CP_COMMIT();
        ldgA(1);                       // ra holds chunk 1
    } else {
        cpA(0, st0); cpB(0, st0); CP_COMMIT();
    }
    CP_WAIT(0);
    __syncthreads();

    // ---- mainloop: ONE sync per chunk --------------------------------------
#pragma unroll
    for (int kc = 0; kc < NC; kc++) {
        const uint32_t cur = (kc & 1) ? st1 : st0;
        const uint32_t nxt = (kc & 1) ? st0 : st1;

        if (kc + 1 < NC) {
            if (!ASPLIT) {
                stcvA(nxt);                     // chunk kc+1 from ra
                if (kc + 2 < NC) ldgA(kc + 2);  // refill ra
            } else {
                cpA(kc + 1, nxt);
            }
            cpB(kc + 1, nxt);
            CP_COMMIT();
        }

        compute(cur);                           // overlaps in-flight loads

        CP_WAIT(0);
        __syncthreads();
    }

    // ---- epilogue -----------------------------------------------------------
    const int gq  = lane >> 2;
    const int tc2 = (lane & 3) * 2;
#pragma unroll
    for (int mb = 0; mb < 2; mb++) {
        int r0 = mtile + wm * 32 + mb * 16 + gq;
#pragma unroll
        for (int nb = 0; nb < 8; nb++) {
            int col = ntile + wn * 64 + nb * 8 + tc2;
            float bv0 = bias[col], bv1 = bias[col + 1];
            float z0 = acc[mb][nb][0] + bv0;
            float z1 = acc[mb][nb][1] + bv1;
            float z2 = acc[mb][nb][2] + bv0;
            float z3 = acc[mb][nb][3] + bv1;
            if (EPI == 1) {
                z0 = z0 * (1.0f / (1.0f + __expf(-z0)));
                z1 = z1 * (1.0f / (1.0f + __expf(-z1)));
                z2 = z2 * (1.0f / (1.0f + __expf(-z2)));
                z3 = z3 * (1.0f / (1.0f + __expf(-z3)));
            }
            if (WSPLIT) {
                float h0 = __bfloat162float(__float2bfloat16(z0));
                float h1 = __bfloat162float(__float2bfloat16(z1));
                float h2v = __bfloat162float(__float2bfloat16(z2));
                float h3 = __bfloat162float(__float2bfloat16(z3));
                *reinterpret_cast<uint32_t*>(&Chi[(size_t)r0 * DD + col]) =
                    pack_bf16x2(z0, z1);
                *reinterpret_cast<uint32_t*>(&Clo[(size_t)r0 * DD + col]) =
                    pack_bf16x2(z0 - h0, z1 - h1);
                *reinterpret_cast<uint32_t*>(&Chi[(size_t)(r0 + 8) * DD + col]) =
                    pack_bf16x2(z2, z3);
                *reinterpret_cast<uint32_t*>(&Clo[(size_t)(r0 + 8) * DD + col]) =
                    pack_bf16x2(z2 - h2v, z3 - h3);
            } else {
                *reinterpret_cast<float2*>(&C[(size_t)r0 * DD + col]) =
                    make_float2(z0, z1);
                *reinterpret_cast<float2*>(&C[(size_t)(r0 + 8) * DD + col]) =
                    make_float2(z2, z3);
            }
        }
    }
}

// ---------------------------------------------------------------------------
// fp32 SIMT GEMM for the small readout MLP
// ---------------------------------------------------------------------------
template <int EPI>
__global__ __launch_bounds__(256, 2)
void gemm128(const float* __restrict__ A, const float* __restrict__ B,
             const float* __restrict__ bias, float* __restrict__ C,
             int M, int Ncols, int K)
{
    constexpr int BM = 128, BN = 128, BK = 16;
    __shared__ float As[BK][BM + 4];
    __shared__ float Bs[BK][BN + 4];

    const int mtile = blockIdx.x * BM;
    const int ntile = blockIdx.y * BN;
    const int tid = threadIdx.x;
    const int trow = tid >> 4;
    const int tcol = tid & 15;

    float acc[8][8];
#pragma unroll
    for (int i = 0; i < 8; i++)
#pragma unroll
        for (int j = 0; j < 8; j++) acc[i][j] = 0.0f;

    for (int k0 = 0; k0 < K; k0 += BK) {
#pragma unroll
        for (int t = 0; t < 2; t++) {
            int f4 = tid + t * 256;
            int r = f4 >> 2;
            int c = (f4 & 3) * 4;
            float4 v = *reinterpret_cast<const float4*>(
                &A[(size_t)(mtile + r) * K + k0 + c]);
            As[c + 0][r] = v.x;
            As[c + 1][r] = v.y;
            As[c + 2][r] = v.z;
            As[c + 3][r] = v.w;
        }
#pragma unroll
        for (int t = 0; t < 2; t++) {
            int f4 = tid + t * 256;
            int r = f4 >> 5;
            int c = (f4 & 31) * 4;
            float4 v = *reinterpret_cast<const float4*>(
                &B[(size_t)(k0 + r) * Ncols + ntile + c]);
            *reinterpret_cast<float4*>(&Bs[r][c]) = v;
        }
        __syncthreads();

#pragma unroll
        for (int kk = 0; kk < BK; kk++) {
            float a[8], b[8];
            float4 a0 = *reinterpret_cast<const float4*>(&As[kk][trow * 8]);
            float4 a1 = *reinterpret_cast<const float4*>(&As[kk][trow * 8 + 4]);
            float4 b0 = *reinterpret_cast<const float4*>(&Bs[kk][tcol * 8]);
            float4 b1 = *reinterpret_cast<const float4*>(&Bs[kk][tcol * 8 + 4]);
            a[0]=a0.x; a[1]=a0.y; a[2]=a0.z; a[3]=a0.w;
            a[4]=a1.x; a[5]=a1.y; a[6]=a1.z; a[7]=a1.w;
            b[0]=b0.x; b[1]=b0.y; b[2]=b0.z; b[3]=b0.w;
            b[4]=b1.x; b[5]=b1.y; b[6]=b1.z; b[7]=b1.w;
#pragma unroll
            for (int i = 0; i < 8; i++)
#pragma unroll
                for (int j = 0; j < 8; j++)
                    acc[i][j] = fmaf(a[i], b[j], acc[i][j]);
        }
        __syncthreads();
    }

    float bv[8];
#pragma unroll
    for (int j = 0; j < 8; j++) bv[j] = bias[ntile + tcol * 8 + j];

#pragma unroll
    for (int i = 0; i < 8; i++) {
        int row = mtile + trow * 8 + i;
        float v[8];
#pragma unroll
        for (int j = 0; j < 8; j++) {
            float z = acc[i][j] + bv[j];
            if (EPI == 1) z = z * (1.0f / (1.0f + __expf(-z)));
            v[j] = z;
        }
        float* cp = &C[(size_t)row * Ncols + ntile + tcol * 8];
        *reinterpret_cast<float4*>(cp)     = make_float4(v[0], v[1], v[2], v[3]);
        *reinterpret_cast<float4*>(cp + 4) = make_float4(v[4], v[5], v[6], v[7]);
    }
}

// ---------------------------------------------------------------------------
// Fused single-pass segment softmax-weighted sum (online softmax)
// ---------------------------------------------------------------------------
__global__ __launch_bounds__(256)
void segment_softmax_kernel(const float* __restrict__ s, const float* __restrict__ x,
                            const int* __restrict__ offs, float* __restrict__ sx)
{
    int b = blockIdx.x;
    int d = threadIdx.x;
    int start = offs[b], end = offs[b + 1];

    const float* sp = s + (size_t)start * DD + d;
    const float* xp = x + (size_t)start * DD + d;

    float m = -INFINITY, se = 0.0f, sex = 0.0f;
    for (int i = start; i < end; i++) {
        float sv = *sp;
        float xv = *xp;
        sp += DD; xp += DD;
        if (sv > m) {
            float c = __expf(m - sv);
            se = se * c + 1.0f;
            sex = sex * c + xv;
            m = sv;
        } else {
            float e = __expf(sv - m);
            se += e;
            sex += e * xv;
        }
    }
    sx[b * DD + d] = (end > start) ? (sex / se) : 0.0f;
}

// ---------------------------------------------------------------------------
extern "C" void kernel_launch(void* const* d_in, const int* in_sizes, int n_in,
                              void* d_out, int out_size)
{
    const float* x     = (const float*)d_in[0];
    const int*   index = (const int*)  d_in[1];
    const float* W1    = (const float*)d_in[2];
    const float* b1    = (const float*)d_in[3];
    const float* W2    = (const float*)d_in[4];
    const float* b2    = (const float*)d_in[5];
    const float* W3    = (const float*)d_in[6];
    const float* b3    = (const float*)d_in[7];
    const float* W4    = (const float*)d_in[8];
    const float* b4    = (const float*)d_in[9];
    float* out = (float*)d_out;

    float *s, *sx, *h2;
    int* offs;
    __nv_bfloat16 *hh, *hl, *w1h, *w1l, *w2h, *w2l;
    cudaGetSymbolAddress((void**)&hh,   g_h_hi);
    cudaGetSymbolAddress((void**)&hl,   g_h_lo);
    cudaGetSymbolAddress((void**)&s,    g_s);
    cudaGetSymbolAddress((void**)&sx,   g_sx);
    cudaGetSymbolAddress((void**)&h2,   g_h2);
    cudaGetSymbolAddress((void**)&offs, g_offs);
    cudaGetSymbolAddress((void**)&w1h,  g_w1t_hi);
    cudaGetSymbolAddress((void**)&w1l,  g_w1t_lo);
    cudaGetSymbolAddress((void**)&w2h,  g_w2t_hi);
    cudaGetSymbolAddress((void**)&w2l,  g_w2t_lo);

    cudaFuncSetAttribute((const void*)mma_gemm_pipe<1, false, true>,
                         cudaFuncAttributeMaxDynamicSharedMemorySize, 2 * STG);
    cudaFuncSetAttribute((const void*)mma_gemm_pipe<0, true, false>,
                         cudaFuncAttributeMaxDynamicSharedMemorySize, 2 * STG);

    // 0. split/transpose weights
    prep_weights_kernel<<<dim3(DD, 2), DD>>>(W1, W2);

    // 1. segment boundaries
    seg_offsets_kernel<<<(SEGS + 1 + 255) / 256, 256>>>(index, offs);

    // 2. h = silu(x @ W1 + b1) -> split bf16 (single-sync pipelined mma.sync)
    mma_gemm_pipe<1, false, true><<<dim3(NN / 128, 2), 256, 2 * STG>>>(
        x, nullptr, nullptr, w1h, w1l, b1, nullptr, hh, hl);

    // 3. s = h @ W2 + b2  (A pre-split, cp.async everywhere)
    mma_gemm_pipe<0, true, false><<<dim3(NN / 128, 2), 256, 2 * STG>>>(
        nullptr, hh, hl, w2h, w2l, b2, s, nullptr, nullptr);

    // 4. fused scatter-softmax + weighted segment sum
    segment_softmax_kernel<<<SEGS, 256>>>(s, x, offs, sx);

    // 5. h2 = silu(sx @ W3 + b3)
    gemm128<1><<<dim3(SEGS / 128, DD / 128), 256>>>(sx, W3, b3, h2, SEGS, DD, DD);

    // 6. out = h2 @ W4 + b4
    gemm128<0><<<dim3(SEGS / 128, DOUT / 128), 256>>>(h2, W4, b4, out, SEGS, DOUT, DD);
}